// round 2
// baseline (speedup 1.0000x reference)
#include <cuda_runtime.h>
#include <math.h>

#define N_NODES 10000
#define N_EDGES 64000
#define RHID 64
#define SQM 5.656854249492381f

__device__ float g_h[N_NODES * 32];
__device__ float g_rf[N_EDGES * RHID];
__device__ float g_A3[2080 * 96];
__device__ float g_asum[N_NODES * 288];
__device__ float g_cnt[N_NODES];

__device__ int   g_cg_ij[11][160];
__device__ float g_cg_v[11][160];
__device__ int   g_cg_off[11][6];

__constant__ int c_PI[11]   = {0,0,0,1,1,1,1,2,2,2,2};
__constant__ int c_PJ[11]   = {0,1,2,0,1,1,2,0,1,2,2};
__constant__ int c_PK[11]   = {0,1,2,1,0,2,1,2,1,0,2};
__constant__ int c_SOFF[3]  = {0,1,4};
__constant__ int c_LD[3]    = {1,3,5};
__constant__ int c_LSLOT[9] = {0,1,1,1,2,2,2,2,2};
__constant__ int c_O2W[3]   = {1,2,6};
__constant__ int c_O2U[5]   = {0,4,5,9,10};

__device__ __forceinline__ int mergecol(int u, int slot) {
    if (slot == 0) return u;
    if (slot < 4)  return 32 + u * 3 + (slot - 1);
    return 128 + u * 5 + (slot - 4);
}

/* -------------------- CG table init (1 block, warp per combo) ------- */
__global__ void mace_init_cg() {
    __shared__ float C[11][125];
    int w = threadIdx.x >> 5, lane = threadIdx.x & 31;
    if (w >= 11) return;
    const float s2 = sqrtf(2.f), s3 = sqrtf(3.f), s5 = sqrtf(5.f), s6 = sqrtf(6.f);
    float B[5][3][3];
    for (int a = 0; a < 5; a++) for (int i = 0; i < 3; i++) for (int j = 0; j < 3; j++) B[a][i][j] = 0.f;
    B[0][0][1] = B[0][1][0] = 1.f / s2;
    B[1][1][2] = B[1][2][1] = 1.f / s2;
    B[2][0][0] = -1.f / s6; B[2][1][1] = -1.f / s6; B[2][2][2] = 2.f / s6;
    B[3][0][2] = B[3][2][0] = 1.f / s2;
    B[4][0][0] = 1.f / s2;  B[4][1][1] = -1.f / s2;
    int combo = w;
    int di = c_LD[c_PI[combo]], dj = c_LD[c_PJ[combo]], dk = c_LD[c_PK[combo]];
    float* Cc = C[combo];
    for (int t = lane; t < 125; t += 32) Cc[t] = 0.f;
    __syncwarp();
    switch (combo) {
        case 0: if (lane == 0) Cc[0] = 1.f; break;
        case 1: if (lane < 3) Cc[(0 * 5 + lane) * 5 + lane] = 1.f / s3; break;
        case 2: if (lane < 5) Cc[(0 * 5 + lane) * 5 + lane] = 1.f / s5; break;
        case 3: if (lane < 3) Cc[(lane * 5 + 0) * 5 + lane] = 1.f / s3; break;
        case 4: if (lane < 3) Cc[(lane * 5 + lane) * 5 + 0] = 1.f / s3; break;
        case 5: for (int t = lane; t < 45; t += 32) { int i = t / 15, j = (t % 15) / 5, k = t % 5;
                    Cc[(i * 5 + j) * 5 + k] = B[k][i][j] / s5; } break;
        case 6: for (int t = lane; t < 45; t += 32) { int i = t / 15, j = (t % 15) / 3, k = t % 3;
                    Cc[(i * 5 + j) * 5 + k] = B[j][i][k] / s5; } break;
        case 7: if (lane < 5) Cc[(lane * 5 + 0) * 5 + lane] = 1.f / s5; break;
        case 8: for (int t = lane; t < 45; t += 32) { int i = t / 9, j = (t % 9) / 3, k = t % 3;
                    Cc[(i * 5 + j) * 5 + k] = B[i][j][k] / s5; } break;
        case 9: if (lane < 5) Cc[(lane * 5 + lane) * 5 + 0] = 1.f / s5; break;
        case 10: {
            float ss = 0.f;
            for (int t = lane; t < 125; t += 32) {
                int a = t / 25, b = (t % 25) / 5, c = t % 5;
                float s = 0.f;
                for (int i = 0; i < 3; i++) for (int j = 0; j < 3; j++) for (int k = 0; k < 3; k++)
                    s += B[a][i][j] * B[b][j][k] * B[c][k][i];
                Cc[(a * 5 + b) * 5 + c] = s; ss += s * s;
            }
            for (int o = 16; o; o >>= 1) ss += __shfl_xor_sync(0xffffffff, ss, o);
            float rn = 1.f / sqrtf(ss);
            __syncwarp();
            for (int t = lane; t < 125; t += 32) Cc[t] *= rn;
        } break;
    }
    __syncwarp();
    if (lane == 0) {
        int pos = 0;
        for (int kk = 0; kk < dk; kk++) {
            g_cg_off[combo][kk] = pos;
            for (int ii = 0; ii < di; ii++) for (int jj = 0; jj < dj; jj++) {
                float v = Cc[(ii * 5 + jj) * 5 + kk];
                if (v != 0.f) { g_cg_ij[combo][pos] = ii * 16 + jj; g_cg_v[combo][pos] = v; pos++; }
            }
        }
        g_cg_off[combo][dk] = pos;
    }
}

/* -------------------- repack edge-GEMM B matrix --------------------- */
__global__ void mace_init_A3(const float* __restrict__ aw, const float* __restrict__ ab) {
    int idx = blockIdx.x * blockDim.x + threadIdx.x;
    if (idx >= 2080 * 96) return;
    int k = idx / 96, n = idx - k * 96;
    int l = n >> 5, ww = n & 31;
    const float rsd[3] = {1.f, 0.57735026918962576f, 0.44721359549995794f};
    float scale = rsd[l] * (1.f / SQM);
    float v;
    if (k < 2048) { int r = k >> 5, u = k & 31; v = aw[r * 3072 + l * 1024 + u * 32 + ww]; }
    else          { int u = k - 2048;           v = ab[l * 1024 + u * 32 + ww]; }
    g_A3[idx] = v * scale;
}

__global__ void mace_zero() {
    int i = blockIdx.x * blockDim.x + threadIdx.x;
    if (i < N_NODES * 288) g_asum[i] = 0.f;
    if (i < N_NODES)       g_cnt[i]  = 0.f;
}

__global__ void mace_h(const float* __restrict__ nf, const float* __restrict__ emb) {
    int z = blockIdx.x * 8 + (threadIdx.x >> 5);
    int ww = threadIdx.x & 31;
    const float* r = nf + z * 32;
    float s = 0.f;
#pragma unroll 8
    for (int u = 0; u < 32; u++) s += r[u] * emb[u * 32 + ww];
    g_h[z * 32 + ww] = s * (1.f / SQM);
}

/* -------------------- edge radial MLP ------------------------------- */
__global__ __launch_bounds__(512) void mace_mlp(
    const int* __restrict__ ei, const float* __restrict__ rad, const float* __restrict__ attr,
    const float* __restrict__ w1, const float* __restrict__ b1,
    const float* __restrict__ w2, const float* __restrict__ b2,
    const float* __restrict__ w3, const float* __restrict__ b3) {
    __shared__ float w1s[24 * 64], w2s[64 * 64], w3s[64 * 64];
    __shared__ float b1s[64], b2s[64], b3s[64];
    __shared__ float rin[8][24], x1[8][64], x2[8][64];
    int tid = threadIdx.x;
    for (int i = tid; i < 1536; i += 512) w1s[i] = w1[i];
    for (int i = tid; i < 4096; i += 512) { w2s[i] = w2[i]; w3s[i] = w3[i]; }
    if (tid < 64) { b1s[tid] = b1[tid]; b2s[tid] = b2[tid]; b3s[tid] = b3[tid]; }
    int eg = tid >> 6, t = tid & 63;
    int e = blockIdx.x * 8 + eg;
    if (t < 8)       rin[eg][t] = rad[e * 8 + t];
    else if (t < 24) rin[eg][t] = attr[e * 16 + (t - 8)];
    __syncthreads();
    float s = b1s[t];
#pragma unroll
    for (int k = 0; k < 24; k++) s += rin[eg][k] * w1s[k * 64 + t];
    s = s / (1.f + expf(-s));
    x1[eg][t] = s;
    __syncthreads();
    s = b2s[t];
#pragma unroll 8
    for (int k = 0; k < 64; k++) s += x1[eg][k] * w2s[k * 64 + t];
    s = s / (1.f + expf(-s));
    x2[eg][t] = s;
    __syncthreads();
    s = b3s[t];
#pragma unroll 8
    for (int k = 0; k < 64; k++) s += x2[eg][k] * w3s[k * 64 + t];
    g_rf[e * 64 + t] = s;
    if (t == 0) atomicAdd(&g_cnt[ei[N_EDGES + e]], 1.f);
}

/* ------------ fused edge GEMM + SH expand + atomic scatter ---------- */
__global__ __launch_bounds__(256) void mace_edge_gemm(
    const int* __restrict__ ei, const float* __restrict__ sh) {
    __shared__ int s_src[64], s_dst[64];
    __shared__ float s_sh[64 * 9];
    __shared__ float Hs[64 * 33];
    __shared__ float RFs[64 * 64];
    __shared__ float At[32 * 96];
    int tid = threadIdx.x;
    int e0 = blockIdx.x * 64;
    for (int i = tid; i < 64; i += 256) { s_src[i] = ei[e0 + i]; s_dst[i] = ei[N_EDGES + e0 + i]; }
    for (int i = tid; i < 576; i += 256) s_sh[i] = sh[e0 * 9 + i];
    __syncthreads();
    for (int i = tid; i < 2048; i += 256) { int e = i >> 5, u = i & 31; Hs[e * 33 + u] = g_h[s_src[e] * 32 + u]; }
    for (int i = tid; i < 4096; i += 256) { int e = i >> 6, r = i & 63; RFs[e * 64 + r] = g_rf[(e0 + e) * 64 + r]; }
    int tx = tid & 31, ty = tid >> 5;
    float acc[8][3];
#pragma unroll
    for (int i = 0; i < 8; i++) { acc[i][0] = 0.f; acc[i][1] = 0.f; acc[i][2] = 0.f; }

    for (int kc = 0; kc < 2080; kc += 32) {
        __syncthreads();
        for (int i = tid; i < 3072; i += 256) {
            int kk = i / 96, n = i - kk * 96;
            At[i] = g_A3[(kc + kk) * 96 + n];
        }
        __syncthreads();
        bool bias = (kc >= 2048);
        int r = kc >> 5;
        float rfv[8];
#pragma unroll
        for (int i = 0; i < 8; i++) {
            rfv[i] = 1.f;
            if (!bias) rfv[i] = RFs[(ty * 8 + i) * 64 + r];
        }
#pragma unroll 4
        for (int kk = 0; kk < 32; kk++) {
            float a0 = At[kk * 96 + tx], a1 = At[kk * 96 + 32 + tx], a2 = At[kk * 96 + 64 + tx];
#pragma unroll
            for (int i = 0; i < 8; i++) {
                int e = ty * 8 + i;
                float p = rfv[i] * Hs[e * 33 + kk];
                acc[i][0] += p * a0; acc[i][1] += p * a1; acc[i][2] += p * a2;
            }
        }
    }
    __syncthreads();
#pragma unroll
    for (int i = 0; i < 8; i++) {
        int e = ty * 8 + i;
        float* ob = &g_asum[s_dst[e] * 288];
        const float* shv = &s_sh[e * 9];
        atomicAdd(ob + tx, acc[i][0] * shv[0]);
        float m1 = acc[i][1];
#pragma unroll
        for (int q = 0; q < 3; q++) atomicAdd(ob + 32 + tx * 3 + q, m1 * shv[1 + q]);
        float m2 = acc[i][2];
#pragma unroll
        for (int q = 0; q < 5; q++) atomicAdd(ob + 128 + tx * 5 + q, m2 * shv[4 + q]);
    }
}

/* -------------------- per-node CG machinery ------------------------- */
template<int DK>
__device__ void path_pair(const float* __restrict__ x, const float* __restrict__ y,
                          const float* __restrict__ Wp, int combo, float* out, float scale,
                          float* sT, float* sRed, int tid) {
    int i = c_PI[combo], j = c_PJ[combo], k = c_PK[combo];
    int ib = c_SOFF[i], jb = c_SOFF[j], kb = c_SOFF[k];
    __syncthreads();
    for (int uv = tid; uv < 1024; uv += 256) {
        int u = uv >> 5, v = uv & 31;
        const float* xr = x + u * 9 + ib;
        const float* yr = y + v * 9 + jb;
#pragma unroll
        for (int kk = 0; kk < DK; kk++) {
            int s = g_cg_off[combo][kk], e = g_cg_off[combo][kk + 1];
            float acc = 0.f;
            for (int t = s; t < e; t++) {
                int ij = g_cg_ij[combo][t];
                acc += xr[ij >> 4] * yr[ij & 15] * g_cg_v[combo][t];
            }
            sT[kk * 1024 + uv] = acc;
        }
    }
    __syncthreads();
    int g = tid >> 5, ww = tid & 31;
    float part[DK];
#pragma unroll
    for (int kk = 0; kk < DK; kk++) part[kk] = 0.f;
    const float* Wg = Wp + g * 128 * 32 + ww;
#pragma unroll 2
    for (int q = 0; q < 128; q += 4) {
        int uv = g * 128 + q;
        float w0 = __ldg(Wg + q * 32), w1 = __ldg(Wg + q * 32 + 32);
        float w2 = __ldg(Wg + q * 32 + 64), w3 = __ldg(Wg + q * 32 + 96);
#pragma unroll
        for (int kk = 0; kk < DK; kk++) {
            float4 tv = *(const float4*)&sT[kk * 1024 + uv];
            part[kk] += tv.x * w0 + tv.y * w1 + tv.z * w2 + tv.w * w3;
        }
    }
#pragma unroll
    for (int kk = 0; kk < DK; kk++) sRed[g * 160 + ww * DK + kk] = part[kk];
    __syncthreads();
    for (int o = tid; o < 32 * DK; o += 256) {
        int wu = o / DK, kk = o - wu * DK;
        float s = 0.f;
#pragma unroll
        for (int g2 = 0; g2 < 8; g2++) s += sRed[g2 * 160 + o];
        out[wu * 9 + kb + kk] += s * scale;
    }
}

__device__ void path_uvu(const float* __restrict__ x, const float* __restrict__ Wp,
                         int combo, float* out, float* sT, int tid) {
    int i = c_PI[combo], j = c_PJ[combo], k = c_PK[combo];
    int dk = c_LD[k], ib = c_SOFF[i], jb = c_SOFF[j], kb = c_SOFF[k];
    __syncthreads();
    for (int uv = tid; uv < 1024; uv += 256) {
        int u = uv >> 5, v = uv & 31;
        const float* xr = x + u * 9 + ib;
        const float* yr = x + v * 9 + jb;
        for (int kk = 0; kk < dk; kk++) {
            int s = g_cg_off[combo][kk], e = g_cg_off[combo][kk + 1];
            float acc = 0.f;
            for (int t = s; t < e; t++) {
                int ij = g_cg_ij[combo][t];
                acc += xr[ij >> 4] * yr[ij & 15] * g_cg_v[combo][t];
            }
            sT[kk * 1024 + uv] = acc;
        }
    }
    __syncthreads();
    int u = tid >> 3, kk = tid & 7;
    if (kk < dk) {
        const float* Wr = Wp + u * 32;
        float s = 0.f;
#pragma unroll 8
        for (int v = 0; v < 32; v++) s += sT[kk * 1024 + u * 32 + v] * __ldg(Wr + v);
        out[u * 9 + kb + kk] += s * (1.f / SQM);
    }
}

__device__ __forceinline__ void run_path(const float* x, const float* y, const float* W,
                                         int combo, float* out, float scale,
                                         float* sT, float* sRed, int tid) {
    int dk = c_LD[c_PK[combo]];
    if (dk == 1)      path_pair<1>(x, y, W, combo, out, scale, sT, sRed, tid);
    else if (dk == 3) path_pair<3>(x, y, W, combo, out, scale, sT, sRed, tid);
    else              path_pair<5>(x, y, W, combo, out, scale, sT, sRed, tid);
}

__device__ void lin_op(const float* in, const float* __restrict__ W, float* out, bool accum, int tid) {
    for (int idx = tid; idx < 288; idx += 256) {
        int ww = idx / 9, slot = idx - ww * 9;
        int l = c_LSLOT[slot];
        const float* Wl = W + l * 1024 + ww;
        float s = 0.f;
#pragma unroll 8
        for (int u = 0; u < 32; u++) s += in[u * 9 + slot] * __ldg(Wl + u * 32);
        s *= (1.f / SQM);
        if (accum) out[idx] += s; else out[idx] = s;
    }
}

/* -------------------- per-node main kernel -------------------------- */
__global__ __launch_bounds__(256) void mace_node(
    const float* __restrict__ nf, const float* __restrict__ lin_o1,
    const float* __restrict__ o2w, const float* __restrict__ o2u,
    const float* __restrict__ o3a, const float* __restrict__ o3b,
    const float* __restrict__ mixw, const float* __restrict__ combw,
    const float* __restrict__ selfw, float* __restrict__ out) {
    __shared__ float sa[288], sb[288], st[288], sm[288], smsg[288];
    __shared__ __align__(16) float sT[5120];
    __shared__ float sRed[1280];
    int z = blockIdx.x, tid = threadIdx.x;
    float inv = 1.f / fmaxf(g_cnt[z], 1.f);
    for (int idx = tid; idx < 288; idx += 256) {
        int u = idx / 9, slot = idx - u * 9;
        sa[idx] = g_asum[z * 288 + mergecol(u, slot)] * inv;
        smsg[idx] = 0.f;
    }
    __syncthreads();
    /* order 0 : b1 = lin(a) */
    lin_op(sa, lin_o1, sb, false, tid); __syncthreads();
    lin_op(sb, mixw, sm, false, tid);   __syncthreads();
    lin_op(sm, combw, smsg, true, tid); __syncthreads();
    /* order 1 : b2 */
    for (int idx = tid; idx < 288; idx += 256) sb[idx] = 0.f;
    __syncthreads();
    for (int p = 0; p < 3; p++)
        run_path(sa, sa, o2w + p * 32768, c_O2W[p], sb, 1.f / 32.f, sT, sRed, tid);
    for (int p = 0; p < 5; p++)
        path_uvu(sa, o2u + p * 1024, c_O2U[p], sb, sT, tid);
    __syncthreads();
    lin_op(sb, mixw + 3072, sm, false, tid);   __syncthreads();
    lin_op(sm, combw + 3072, smsg, true, tid); __syncthreads();
    /* order 2 : b3 = pair(pair(a,a,o3a), a, o3b) */
    for (int idx = tid; idx < 288; idx += 256) st[idx] = 0.f;
    __syncthreads();
    for (int p = 0; p < 11; p++)
        run_path(sa, sa, o3a + p * 32768, p, st, 1.f / 32.f, sT, sRed, tid);
    __syncthreads();
    for (int idx = tid; idx < 288; idx += 256) sb[idx] = 0.f;
    __syncthreads();
    for (int p = 0; p < 11; p++)
        run_path(st, sa, o3b + p * 32768, p, sb, 1.f / 32.f, sT, sRed, tid);
    __syncthreads();
    lin_op(sb, mixw + 6144, sm, false, tid);   __syncthreads();
    lin_op(sm, combw + 6144, smsg, true, tid); __syncthreads();
    /* self interaction -> l=0 slot */
    if (tid < 32) {
        float s = 0.f;
        const float* r = nf + z * 32;
#pragma unroll 8
        for (int v = 0; v < 32; v++) s += r[v] * __ldg(selfw + v * 32 + tid);
        smsg[tid * 9] += s * (1.f / SQM);
    }
    __syncthreads();
    for (int idx = tid; idx < 288; idx += 256) {
        int u = idx / 9, slot = idx - u * 9;
        out[z * 288 + mergecol(u, slot)] = smsg[idx];
    }
}

/* -------------------- launch ---------------------------------------- */
extern "C" void kernel_launch(void* const* d_in, const int* in_sizes, int n_in,
                              void* d_out, int out_size) {
    const float* nf    = (const float*)d_in[0];
    const int*   ei    = (const int*)d_in[1];
    const float* sh    = (const float*)d_in[2];
    const float* rad   = (const float*)d_in[3];
    const float* attr  = (const float*)d_in[4];
    const float* w1    = (const float*)d_in[5];
    const float* b1    = (const float*)d_in[6];
    const float* w2    = (const float*)d_in[7];
    const float* b2    = (const float*)d_in[8];
    const float* w3    = (const float*)d_in[9];
    const float* b3    = (const float*)d_in[10];
    const float* aw    = (const float*)d_in[11];
    const float* ab    = (const float*)d_in[12];
    const float* emb   = (const float*)d_in[13];
    const float* lino1 = (const float*)d_in[14];
    const float* o2w   = (const float*)d_in[15];
    const float* o2u   = (const float*)d_in[16];
    const float* o3a   = (const float*)d_in[17];
    const float* o3b   = (const float*)d_in[18];
    const float* mixw  = (const float*)d_in[19];
    const float* combw = (const float*)d_in[20];
    const float* selfw = (const float*)d_in[21];

    mace_init_cg<<<1, 352>>>();
    mace_init_A3<<<(2080 * 96 + 255) / 256, 256>>>(aw, ab);
    mace_zero<<<(N_NODES * 288 + 255) / 256, 256>>>();
    mace_h<<<N_NODES / 8, 256>>>(nf, emb);
    mace_mlp<<<N_EDGES / 8, 512>>>(ei, rad, attr, w1, b1, w2, b2, w3, b3);
    mace_edge_gemm<<<N_EDGES / 64, 256>>>(ei, sh);
    mace_node<<<N_NODES, 256>>>(nf, lino1, o2w, o2u, o3a, o3b, mixw, combw, selfw,
                                (float*)d_out);
}